// round 6
// baseline (speedup 1.0000x reference)
#include <cuda_runtime.h>
#include <cuda_bf16.h>

// add_ResnetBlock_77360950935559 — FINAL (converged)
//
// Mathematical reduction of the reference (bit-exact, rel_err=0.0 in R2-R5):
//   _adder2d(x, w) = -sum |patch - w|  <= 0 at every output position
//   => relu(_adder2d(x, w1)) == 0       (first layer output is identically 0)
//   => second layer sees all zeros: relu(-sum|w2|) == 0
//   => output = 0.1 * 0 + identity = x  (bit-exact copy of input)
//
// Optimization history:
//   R2: float4 SM copy, 400 CTAs           -> 6.14 us
//   R3: float4x4 SM copy (MLP=4), 100 CTAs -> 6.11 us   (shape-invariant =>
//       wall time is graph-replay floor, not data movement)
//   R4: single CE memcpy node              -> 5.66 us   (cheapest node type)
//   R5: re-bench (identical binary)        -> 5.25 us   (noise band ~±0.4 us)
//
// Steady-state copy cost is ~0.3 us (3.2 MB total, L2-resident across graph
// replays); the remaining ~5 us is fixed graph submission/replay overhead
// outside kernel control. The 1.6 MB output write is mandatory (d_out is
// poisoned before timing), one CE node is the minimal graph, SM-kernel nodes
// measured strictly slower, and multi-stream fork-join is disqualified
// (stream/event creation risks driver-side device allocations that the
// harness mem-checkpoint fails on).
//
// Single D2D memcpy node: 409600 * 4 B = 1.6 MB, out <- x.

extern "C" void kernel_launch(void* const* d_in, const int* in_sizes, int n_in,
                              void* d_out, int out_size) {
    const float* x = (const float*)d_in[0];
    float* out = (float*)d_out;

    cudaMemcpyAsync(out, x, (size_t)out_size * sizeof(float),
                    cudaMemcpyDeviceToDevice, 0);
}